// round 7
// baseline (speedup 1.0000x reference)
#include <cuda_runtime.h>

#define MARGIN 0.1f
#define RPB 4                   // rows per batch (one int4 of labels)
#define NUM_BLOCKS 592          // 148 SMs * 4 CTAs -> single wave

// Persistent device scratch (no allocations allowed). Reset by the last block
// each call, so every graph replay sees the same initial state.
__device__ double       g_total = 0.0;
__device__ unsigned int g_count = 0u;

__global__ void __launch_bounds__(256, 4)
margin_loss_kernel(const float* __restrict__ x,
                   const int* __restrict__ labels,   // int32 (JAX x64 disabled)
                   float* __restrict__ out,
                   int N)
{
    const int lane     = threadIdx.x & 31;
    const int warp_gid = (blockIdx.x * blockDim.x + threadIdx.x) >> 5;
    const int nwarps   = (NUM_BLOCKS * 256) >> 5;      // 4736
    const int nbatch   = N / RPB;

    const float4* x4   = reinterpret_cast<const float4*>(x);
    const int4*   lab4 = reinterpret_cast<const int4*>(labels);

    float wsum  = 0.0f;     // per-thread hinge accumulator
    int   nrows = 0;        // rows this warp processed (for the -MARGIN fixup)

    float4 vA[RPB], vB[RPB];
    float  cA[RPB], cB[RPB];
    int4   lA, lB;

    // Issue c-gather (uniform address -> one 32B sector, HW broadcast) and the
    // streaming row loads for batch bb. Labels L arrived >= 1 iteration ago,
    // so there is NO dependent-load stall here.
    auto load_cv = [&](int bb, const int4& L, float* cc, float4* vv) {
        const size_t base = (size_t)bb * RPB;
        const int l0 = L.x, l1 = L.y, l2 = L.z, l3 = L.w;
        cc[0] = __ldg(&x[(base + 0) * 128 + l0]);
        cc[1] = __ldg(&x[(base + 1) * 128 + l1]);
        cc[2] = __ldg(&x[(base + 2) * 128 + l2]);
        cc[3] = __ldg(&x[(base + 3) * 128 + l3]);
        #pragma unroll
        for (int k = 0; k < RPB; k++)
            vv[k] = __ldcs(&x4[(base + k) * 32 + lane]);
    };

    auto compute = [&](const float4* vv, const float* cc) {
        #pragma unroll
        for (int k = 0; k < RPB; k++) {
            const float m = MARGIN - cc[k];
            wsum += fmaxf(m + vv[k].x, 0.0f);
            wsum += fmaxf(m + vv[k].y, 0.0f);
            wsum += fmaxf(m + vv[k].z, 0.0f);
            wsum += fmaxf(m + vv[k].w, 0.0f);
        }
        nrows += RPB;
    };

    int b = warp_gid;
    if (b < nbatch) {
        // Prologue: one exposed label->gather stall, then the pipeline is full.
        lA = __ldg(&lab4[b]);
        load_cv(b, lA, cA, vA);
        {
            const int b1 = b + nwarps;
            if (b1 < nbatch) lB = __ldg(&lab4[b1]);
        }

        for (;;) {
            const int b1 = b + nwarps;
            if (b1 >= nbatch) { compute(vA, cA); break; }

            // Phase A: prefetch batch b1 (labels lB already resident),
            // fetch labels for b2 into lA, compute batch b.
            load_cv(b1, lB, cB, vB);
            const int b2 = b1 + nwarps;
            if (b2 < nbatch) lA = __ldg(&lab4[b2]);
            compute(vA, cA);

            if (b2 >= nbatch) { compute(vB, cB); break; }

            // Phase B: symmetric.
            load_cv(b2, lA, cA, vA);
            const int b3 = b2 + nwarps;
            if (b3 < nbatch) lB = __ldg(&lab4[b3]);
            compute(vB, cB);

            b = b2;
        }
    }

    // One warp reduction for everything this warp processed.
    #pragma unroll
    for (int o = 16; o > 0; o >>= 1)
        wsum += __shfl_down_sync(0xffffffffu, wsum, o);
    // Each processed row's j==label term contributed exactly MARGIN; remove.
    if (lane == 0) wsum -= MARGIN * (float)nrows;

    __shared__ float warp_sums[8];
    __shared__ bool  is_last;

    if (lane == 0) warp_sums[threadIdx.x >> 5] = wsum;
    __syncthreads();

    if (threadIdx.x == 0) {
        double bsum = 0.0;
        #pragma unroll
        for (int wi = 0; wi < 8; wi++) bsum += (double)warp_sums[wi];
        atomicAdd(&g_total, bsum);
        __threadfence();
        unsigned int t = atomicAdd(&g_count, 1u);
        is_last = (t == gridDim.x - 1);
    }
    __syncthreads();

    if (is_last && threadIdx.x == 0) {
        const double total = g_total;
        // mean over N * (G-1) pairs, G = 128
        out[0] = (float)(total / ((double)N * 127.0));
        // Reset for the next (graph-replayed) call.
        g_total = 0.0;
        g_count = 0u;
    }
}

extern "C" void kernel_launch(void* const* d_in, const int* in_sizes, int n_in,
                              void* d_out, int out_size)
{
    const float* x      = (const float*)d_in[0];
    const int*   labels = (const int*)d_in[1];
    float*       out    = (float*)d_out;

    const int N = in_sizes[1];                  // labels count = rows

    margin_loss_kernel<<<NUM_BLOCKS, 256>>>(x, labels, out, N);
}